// round 15
// baseline (speedup 1.0000x reference)
#include <cuda_runtime.h>
#include <cuda_bf16.h>
#include <math.h>

#define BB   64
#define TL   383
#define SL   384
#define DL   896
#define HG   400
#define HEH  256
#define TAGL 128
#define MST  20
#define MR   (BB*SL)    // 24576
#define NPRE 896        // padded 2*HG
#define XW   448        // X fragment words per row (K=896)
#define GW   400        // GS fragment words per row (K=800)

// ---------------- scratch (device globals) ----------------
__device__ float g_Mf[MR];
__device__ float g_Pre[(size_t)MR*NPRE];
__device__ float g_biasFB[NPRE];
__device__ float g_biasE[HEH];
__device__ float g_biasTag[2*TAGL];
__device__ unsigned g_Xfh[(size_t)MR*XW];
__device__ unsigned g_Xfl[(size_t)MR*XW];
__device__ unsigned g_GSfh[(size_t)MR*GW];
__device__ unsigned g_GSfl[(size_t)MR*GW];
__device__ unsigned g_Be[16*2*2048];
__device__ unsigned g_Bp[50*2*2048];
__device__ unsigned g_Bpre[56*2*7168];
__device__ unsigned g_Btag[50*2*2048];
__device__ unsigned g_Bw[16*25600];
__device__ unsigned g_HXP[8*2*2*16*200];
__device__ unsigned g_secCnt[4];   // Pre progress per t-section (448 tiles each)

#define CLUSTER_SYNC_() do { \
    asm volatile("barrier.cluster.arrive.aligned;" ::: "memory"); \
    asm volatile("barrier.cluster.wait.aligned;" ::: "memory"); \
} while (0)

// ---------------- helpers ----------------
__device__ __forceinline__ unsigned ld_acq(const unsigned* p) {
    unsigned v;
    asm volatile("ld.acquire.gpu.u32 %0, [%1];" : "=r"(v) : "l"(p) : "memory");
    return v;
}

__device__ __forceinline__ void splitpack(float x0, float x1, unsigned& hi, unsigned& lo) {
    __nv_bfloat16 b0 = __float2bfloat16_rn(x0);
    __nv_bfloat16 b1 = __float2bfloat16_rn(x1);
    float r0 = x0 - __bfloat162float(b0);
    float r1 = x1 - __bfloat162float(b1);
    __nv_bfloat16 c0 = __float2bfloat16_rn(r0);
    __nv_bfloat16 c1 = __float2bfloat16_rn(r1);
    hi = (unsigned)__bfloat16_as_ushort(b0) | ((unsigned)__bfloat16_as_ushort(b1) << 16);
    lo = (unsigned)__bfloat16_as_ushort(c0) | ((unsigned)__bfloat16_as_ushort(c1) << 16);
}

__device__ __forceinline__ void mma16816(float* d, unsigned a0, unsigned a1, unsigned a2,
                                         unsigned a3, unsigned b0, unsigned b1) {
    asm volatile(
        "mma.sync.aligned.m16n8k16.row.col.f32.bf16.bf16.f32 "
        "{%0,%1,%2,%3},{%4,%5,%6,%7},{%8,%9},{%0,%1,%2,%3};"
        : "+f"(d[0]), "+f"(d[1]), "+f"(d[2]), "+f"(d[3])
        : "r"(a0), "r"(a1), "r"(a2), "r"(a3), "r"(b0), "r"(b1));
}

__device__ __forceinline__ float tanhfast(float x) {
    float e = __expf(2.f * x);
    return 1.f - __fdividef(2.f, e + 1.f);
}

__device__ __forceinline__ int word_of_k(int k) {
    int kt = k >> 4, rem = k & 15;
    int s = (rem < 8) ? rem : (rem - 7);
    return kt * 8 + s;
}

// ---------------- setup (split: main / side) ----------------
#define S1 (56*2*7168)
#define S6 (NPRE)
#define TXW ((size_t)MR*XW)
#define TMAIN ((size_t)S1 + S6 + TXW + MR)

__global__ void k_setup_main(const float* __restrict__ Wih_f, const float* __restrict__ Wih_b,
                             const float* __restrict__ bih_f, const float* __restrict__ bhh_f,
                             const float* __restrict__ bih_b, const float* __restrict__ bhh_b,
                             const float* __restrict__ inp, const float* __restrict__ tag,
                             const float* __restrict__ sent, const int* __restrict__ mask) {
    if (blockIdx.x == 0 && threadIdx.x < 4) g_secCnt[threadIdx.x] = 0u;
    size_t gidx = (size_t)blockIdx.x * blockDim.x + threadIdx.x;
    if (gidx < S1) {
        int idx = (int)gidx;
        int kt = idx / 14336, rest = idx % 14336;
        int split = rest / 7168, w = rest % 7168;
        int n = w >> 3, s = w & 7;
        int k = kt * 16 + 2 * (s >> 1) + 8 * (s & 1);
        float x0 = 0.f, x1 = 0.f;
        if (n < HG)          { x0 = Wih_f[(size_t)n * DL + k];        x1 = Wih_f[(size_t)n * DL + k + 1]; }
        else if (n < 2*HG)   { x0 = Wih_b[(size_t)(n-HG) * DL + k];   x1 = Wih_b[(size_t)(n-HG) * DL + k + 1]; }
        unsigned hi, lo; splitpack(x0, x1, hi, lo);
        g_Bpre[idx] = split ? lo : hi; return;
    }
    gidx -= S1;
    if (gidx < S6) {
        int idx = (int)gidx;
        float v = 0.f;
        if (idx < HG) v = bih_f[idx] + bhh_f[idx];
        else if (idx < 2*HG) v = bih_b[idx-HG] + bhh_b[idx-HG];
        g_biasFB[idx] = v; return;
    }
    gidx -= S6;
    if (gidx < TXW) {
        int p = (int)(gidx % XW);
        int r = (int)(gidx / XW);
        int k = (p >> 3) * 16 + 2 * ((p & 7) >> 1) + 8 * ((p & 7) & 1);
        int b = r / SL, s = r % SL;
        float x0, x1;
        if (s == 0) { x0 = sent[k]; x1 = sent[k + 1]; }
        else {
            int t = s - 1;
            if (k < 768) {
                const float* base = inp + (size_t)(b * TL + t) * 768;
                x0 = base[k]; x1 = base[k + 1];
            } else {
                const float* base = tag + (size_t)(b * TL + t) * TAGL;
                x0 = base[k - 768]; x1 = base[k - 767];
            }
        }
        unsigned hi, lo; splitpack(x0, x1, hi, lo);
        g_Xfh[gidx] = hi;
        g_Xfl[gidx] = lo;
        return;
    }
    gidx -= TXW;
    if (gidx < MR) {
        int b = (int)(gidx / SL), s = (int)(gidx % SL);
        g_Mf[gidx] = (s == 0) ? 1.0f : (float)mask[b * TL + s - 1];
    }
}

#define P2 (50*2*2048)
#define P3 (16*2*2048)
#define P4 (50*2*2048)
#define P5 (16*25600)
#define P7 (HEH)
#define P8 (2*TAGL)
#define TSIDE (P2+P3+P4+P5+P7+P8)

__global__ void k_setup_side(const float* __restrict__ Wg2e, const float* __restrict__ Whh_e,
                             const float* __restrict__ Wht,  const float* __restrict__ Wdt,
                             const float* __restrict__ Whh_f, const float* __restrict__ Whh_b,
                             const float* __restrict__ bih_e, const float* __restrict__ bhh_e,
                             const float* __restrict__ bht,   const float* __restrict__ bdt) {
    int idx = blockIdx.x * blockDim.x + threadIdx.x;
    if (idx < P2) {
        int kt = idx >> 12, rest = idx & 4095;
        int split = rest >> 11, w = rest & 2047;
        int n = w >> 3, s = w & 7;
        int k = kt * 16 + 2 * (s >> 1) + 8 * (s & 1);
        float x0 = Wg2e[(size_t)n * (2*HG) + k];
        float x1 = Wg2e[(size_t)n * (2*HG) + k + 1];
        unsigned hi, lo; splitpack(x0, x1, hi, lo);
        g_Bp[idx] = split ? lo : hi; return;
    }
    idx -= P2;
    if (idx < P3) {
        int kt = idx >> 12, rest = idx & 4095;
        int split = rest >> 11, w = rest & 2047;
        int n = w >> 3, s = w & 7;
        int k = kt * 16 + 2 * (s >> 1) + 8 * (s & 1);
        float x0 = Whh_e[(size_t)n * HEH + k];
        float x1 = Whh_e[(size_t)n * HEH + k + 1];
        unsigned hi, lo; splitpack(x0, x1, hi, lo);
        g_Be[idx] = split ? lo : hi; return;
    }
    idx -= P3;
    if (idx < P4) {
        int kt = idx >> 12, rest = idx & 4095;
        int split = rest >> 11, w = rest & 2047;
        int n = w >> 3, s = w & 7;
        int k = kt * 16 + 2 * (s >> 1) + 8 * (s & 1);
        float x0, x1;
        if (n < TAGL) { x0 = Wht[(size_t)n * (2*HG) + k];        x1 = Wht[(size_t)n * (2*HG) + k + 1]; }
        else          { x0 = Wdt[(size_t)(n-TAGL) * (2*HG) + k]; x1 = Wdt[(size_t)(n-TAGL) * (2*HG) + k + 1]; }
        unsigned hi, lo; splitpack(x0, x1, hi, lo);
        g_Btag[idx] = split ? lo : hi; return;
    }
    idx -= P4;
    if (idx < P5) {
        int ctx = idx / 25600, rest = idx % 25600;
        int dir = ctx >> 3, jgx = ctx & 7;
        int kt = rest >> 10, r2 = rest & 1023;
        int split = r2 >> 9, r3 = r2 & 511;
        int n = r3 >> 3, s = r3 & 7;
        int k = kt * 16 + 2 * (s >> 1) + 8 * (s & 1);
        float x0 = 0.f, x1 = 0.f;
        if (n < 50) {
            const float* W = dir ? Whh_b : Whh_f;
            int j = jgx * 50 + n;
            x0 = W[(size_t)j * HG + k];
            x1 = W[(size_t)j * HG + k + 1];
        }
        unsigned hi, lo; splitpack(x0, x1, hi, lo);
        g_Bw[idx] = split ? lo : hi; return;
    }
    idx -= P5;
    if (idx < P7) { g_biasE[idx] = bih_e[idx] + bhh_e[idx]; return; }
    idx -= P7;
    if (idx < P8) g_biasTag[idx] = (idx < TAGL) ? bht[idx] : bdt[idx - TAGL];
}

// ---------------- split-bf16 HMMA GEMM, 128x128 tile ----------------
template <int ACT, int PROG>
__global__ __launch_bounds__(256) void k_hgemm(const unsigned* __restrict__ Afh,
                                               const unsigned* __restrict__ Afl,
                                               const unsigned* __restrict__ Bfrag,
                                               const float* __restrict__ bias,
                                               float* __restrict__ C, float* __restrict__ C2,
                                               int N, int nkt, int Kw, int Nfrag) {
    __shared__ __align__(16) unsigned Ahs[2][1024];
    __shared__ __align__(16) unsigned Als[2][1024];
    __shared__ __align__(16) unsigned Bsm[2][2048];
    int yy = blockIdx.y, ymap, sec = 0;
    if (PROG) {
        if (yy < 64)       { ymap = yy * 3;            sec = 0; }
        else if (yy < 128) { ymap = (yy - 64) * 3 + 2; sec = 2; }
        else               { ymap = (yy - 128) * 3 + 1; sec = 1; }
    } else ymap = yy;
    int m0 = ymap * 128, n0 = blockIdx.x * 128;
    int tid = threadIdx.x, wid = tid >> 5, lane = tid & 31;
    int mw = wid & 3, nh = wid >> 2;
    int r4 = lane >> 2, c4 = lane & 3;
    int Nw8 = Nfrag * 8;

    int arow = tid >> 1, sg = (tid & 1) * 4;
    const unsigned* Aph = Afh + (size_t)(m0 + arow) * Kw + sg;
    const unsigned* Apl = Afl + (size_t)(m0 + arow) * Kw + sg;

    uint4 afh, afl;
    uint2 bf[4];
    float acc[2][8][4];
#pragma unroll
    for (int mt = 0; mt < 2; mt++)
#pragma unroll
        for (int nt = 0; nt < 8; nt++)
#pragma unroll
            for (int q = 0; q < 4; q++) acc[mt][nt][q] = 0.f;

#define HLD(KT) do { \
        afh = *(const uint4*)(Aph + (size_t)(KT) * 8); \
        afl = *(const uint4*)(Apl + (size_t)(KT) * 8); \
        _Pragma("unroll") for (int i_ = 0; i_ < 4; i_++) { \
            int lw = 2 * (i_ * 256 + tid); \
            int sp = lw >> 10, wq = lw & 1023; \
            bf[i_] = *(const uint2*)(Bfrag + (size_t)(KT) * 2 * Nw8 + (size_t)sp * Nw8 + n0 * 8 + wq); } \
    } while (0)

#define HST(BUF) do { \
        *(uint4*)&Ahs[BUF][arow * 8 + sg] = afh; \
        *(uint4*)&Als[BUF][arow * 8 + sg] = afl; \
        _Pragma("unroll") for (int i_ = 0; i_ < 4; i_++) \
            *(uint2*)&Bsm[BUF][2 * (i_ * 256 + tid)] = bf[i_]; \
    } while (0)

    HLD(0);
    HST(0);
    __syncthreads();
    for (int kt = 0; kt < nkt; kt++) {
        int buf = kt & 1;
        if (kt + 1 < nkt) HLD(kt + 1);
        uint2 Uh[2], Vh[2], Ul[2], Vl[2];
#pragma unroll
        for (int mt = 0; mt < 2; mt++) {
            int rb = mw * 32 + mt * 16 + r4;
            Uh[mt] = *(uint2*)&Ahs[buf][rb * 8 + 2 * c4];
            Vh[mt] = *(uint2*)&Ahs[buf][(rb + 8) * 8 + 2 * c4];
            Ul[mt] = *(uint2*)&Als[buf][rb * 8 + 2 * c4];
            Vl[mt] = *(uint2*)&Als[buf][(rb + 8) * 8 + 2 * c4];
        }
#pragma unroll
        for (int nt = 0; nt < 8; nt++) {
            int n = nh * 64 + nt * 8 + r4;
            uint2 Bh = *(uint2*)&Bsm[buf][n * 8 + 2 * c4];
            uint2 Bl = *(uint2*)&Bsm[buf][1024 + n * 8 + 2 * c4];
#pragma unroll
            for (int mt = 0; mt < 2; mt++) {
                mma16816(acc[mt][nt], Uh[mt].x, Vh[mt].x, Uh[mt].y, Vh[mt].y, Bh.x, Bh.y);
                mma16816(acc[mt][nt], Uh[mt].x, Vh[mt].x, Uh[mt].y, Vh[mt].y, Bl.x, Bl.y);
                mma16816(acc[mt][nt], Ul[mt].x, Vl[mt].x, Ul[mt].y, Vl[mt].y, Bh.x, Bh.y);
            }
        }
        if (kt + 1 < nkt) HST(buf ^ 1);
        __syncthreads();
    }
#undef HLD
#undef HST

#pragma unroll
    for (int nt = 0; nt < 8; nt++) {
        int colL = nh * 64 + nt * 8 + 2 * c4;
        float b0 = bias[n0 + colL], b1 = bias[n0 + colL + 1];
#pragma unroll
        for (int mt = 0; mt < 2; mt++) {
            int r = m0 + mw * 32 + mt * 16 + r4;
            float v0 = acc[mt][nt][0] + b0, v1 = acc[mt][nt][1] + b1;
            float v2 = acc[mt][nt][2] + b0, v3 = acc[mt][nt][3] + b1;
            if (ACT == 2) {
                v0 = (v0 > 0.f) ? v0 : expm1f(v0);
                v1 = (v1 > 0.f) ? v1 : expm1f(v1);
                v2 = (v2 > 0.f) ? v2 : expm1f(v2);
                v3 = (v3 > 0.f) ? v3 : expm1f(v3);
                float* dst = (blockIdx.x == 0) ? C : C2;
                *(float2*)(dst + (size_t)r * TAGL + colL)       = make_float2(v0, v1);
                *(float2*)(dst + (size_t)(r + 8) * TAGL + colL) = make_float2(v2, v3);
            } else {
                *(float2*)(C + (size_t)r * N + n0 + colL)       = make_float2(v0, v1);
                *(float2*)(C + (size_t)(r + 8) * N + n0 + colL) = make_float2(v2, v3);
            }
        }
    }
    if (PROG) {
        __threadfence();
        __syncthreads();
        if (tid == 0) atomicAdd(&g_secCnt[sec], 1u);
    }
}

// ---------------- HMMA bidirectional masked RNN (8 clusters of 8, 16 batches/CTA) ----------------
#define RAS 200
#define RNN_SMEM ((25600 + 2*16*RAS) * 4)

__global__ void __cluster_dims__(8, 1, 1) __launch_bounds__(256, 1) k_rnn() {
    extern __shared__ unsigned rsm[];
    unsigned* Bs = rsm;
    unsigned* Ah = rsm + 25600;
    unsigned* Al = Ah + 16 * RAS;

    int bx = blockIdx.x;
    int cl = bx >> 3, jg = bx & 7;
    int dir = cl >> 2, bg = cl & 3;
    int bbase = bg * 16;
    int tid = threadIdx.x, wid = tid >> 5, lane = tid & 31;
    int ng = wid;
    int r4 = lane >> 2, c4 = lane & 3;
    int rlo = r4, rhi = r4 + 8;

    {
        const uint2* bsrc = (const uint2*)(g_Bw + (size_t)(dir * 8 + jg) * 25600);
#pragma unroll
        for (int i = 0; i < 50; i++) {
            int idx = tid + i * 256;
            uint2 v = __ldcg(bsrc + idx);
            *(uint2*)&Bs[2 * idx] = v;
        }
    }
    {
        unsigned* hxp0 = g_HXP + (size_t)(cl * 2 + 0) * 6400;
        for (int idx = tid; idx < 800; idx += 256) {
            int split = idx / 400, rest = idx % 400;
            int b = rest / 25, w = rest % 25;
            int p = word_of_k(jg * 50 + 2 * w);
            __stcg(&hxp0[split * 3200 + b * 200 + p], 0u);
        }
    }
    __syncthreads();
    CLUSTER_SYNC_();

    int jl = ng * 8 + 2 * c4;
    int valid = (jl < 50);
    int wdp = word_of_k(jg * 50 + jl);
    int wdg = word_of_k(dir * 400 + jg * 50 + jl);
    float h[2][2];
#pragma unroll
    for (int a = 0; a < 2; a++) { h[a][0] = 0.f; h[a][1] = 0.f; }

    for (int tv = 0; tv < SL; tv++) {
        int t = dir ? (SL - 1 - tv) : tv;
        // gate on Pre progress at section boundaries (3 polls total)
        if (tv == 0 || tv == 128 || tv == 256) {
            int sec = t >> 7;
            if (tid == 0) {
                while (ld_acq(&g_secCnt[sec]) < 448u) { __nanosleep(256); }
            }
            __syncthreads();
        }
        int pp = tv & 1;
        const uint2* src = (const uint2*)(g_HXP + (size_t)(cl * 2 + pp) * 6400);
        uint2 bp[13];
#pragma unroll
        for (int i = 0; i < 13; i++) {
            int idx = tid + i * 256;
            if (idx < 3200) {
                int split = idx / 1600, rest = idx % 1600;
                int b = rest / 100, wp = rest % 100;
                bp[i] = __ldcg(src + (size_t)split * 1600 + b * 100 + wp);
            }
        }
        float mv[2];
        mv[0] = g_Mf[(bbase + rlo) * SL + t];
        mv[1] = g_Mf[(bbase + rhi) * SL + t];
        float2 pre[2];
#pragma unroll
        for (int rq = 0; rq < 2; rq++) {
            int R = rq ? rhi : rlo;
            pre[rq] = *(const float2*)(g_Pre + (size_t)((bbase + R) * SL + t) * NPRE + dir * HG + jg * 50 + jl);
        }
#pragma unroll
        for (int i = 0; i < 13; i++) {
            int idx = tid + i * 256;
            if (idx < 3200) {
                int split = idx / 1600, rest = idx % 1600;
                int b = rest / 100, wp = rest % 100;
                unsigned* dst = split ? Al : Ah;
                *(uint2*)&dst[b * RAS + wp * 2] = bp[i];
            }
        }
        __syncthreads();

        float fa[2][3][4];
#pragma unroll
        for (int px = 0; px < 2; px++)
#pragma unroll
            for (int tm = 0; tm < 3; tm++)
#pragma unroll
                for (int z = 0; z < 4; z++) fa[px][tm][z] = 0.f;
#pragma unroll
        for (int kt = 0; kt < 25; kt++) {
            int px = kt & 1;
            uint2 UA  = *(uint2*)&Ah[rlo * RAS + kt * 8 + 2 * c4];
            uint2 VA  = *(uint2*)&Ah[rhi * RAS + kt * 8 + 2 * c4];
            uint2 UAl = *(uint2*)&Al[rlo * RAS + kt * 8 + 2 * c4];
            uint2 VAl = *(uint2*)&Al[rhi * RAS + kt * 8 + 2 * c4];
            int n = ng * 8 + r4;
            uint2 Bh = *(uint2*)&Bs[(kt * 2) * 512 + n * 8 + 2 * c4];
            uint2 Bl = *(uint2*)&Bs[(kt * 2 + 1) * 512 + n * 8 + 2 * c4];
            mma16816(fa[px][0], UA.x, VA.x, UA.y, VA.y, Bh.x, Bh.y);
            mma16816(fa[px][1], UA.x, VA.x, UA.y, VA.y, Bl.x, Bl.y);
            mma16816(fa[px][2], UAl.x, VAl.x, UAl.y, VAl.y, Bh.x, Bh.y);
        }
        float acc[4];
#pragma unroll
        for (int z = 0; z < 4; z++)
            acc[z] = ((fa[0][0][z] + fa[0][1][z]) + (fa[0][2][z] + fa[1][0][z]))
                   + (fa[1][1][z] + fa[1][2][z]);
        // no __syncthreads: end-of-step cluster barrier covers CTA-level too

        unsigned* dsth = g_HXP + (size_t)(cl * 2 + (pp ^ 1)) * 6400;
#pragma unroll
        for (int rq = 0; rq < 2; rq++) {
            int R = rq ? rhi : rlo;
            float mt = mv[rq], om = 1.f - mt;
            float u0 = mt * tanhfast(pre[rq].x + acc[rq * 2 + 0]) + om * h[rq][0];
            float u1 = mt * tanhfast(pre[rq].y + acc[rq * 2 + 1]) + om * h[rq][1];
            h[rq][0] = u0; h[rq][1] = u1;
            if (valid) {
                unsigned hi, lo; splitpack(u0, u1, hi, lo);
                __stcg(&dsth[R * 200 + wdp], hi);
                __stcg(&dsth[3200 + R * 200 + wdp], lo);
                size_t row = (size_t)((bbase + R) * SL + t);
                unsigned gh = (mt != 0.f) ? hi : 0u;
                unsigned gl = (mt != 0.f) ? lo : 0u;
                __stcg(&g_GSfh[row * GW + wdg], gh);
                __stcg(&g_GSfl[row * GW + wdg], gl);
            }
        }
        CLUSTER_SYNC_();
    }
}

// ---------------- tensor-core proj + 20-step estep loop (64 rows/CTA, 2 CTAs/SM) ----------------
#define AST 136
#define ELOOP_WORDS (2*8704 + 8192 + 1024 + 64 + 128)
#define ELOOP_SMEM  (ELOOP_WORDS * 4)

__global__ __launch_bounds__(256, 2) void k_eloop(const float* __restrict__ wie,
                                                  const float* __restrict__ wcls,
                                                  const float* __restrict__ bcls,
                                                  const float* __restrict__ bos,
                                                  const float* __restrict__ bg2e,
                                                  float* __restrict__ outArc) {
    extern __shared__ unsigned sm_u[];
    unsigned* Ah  = sm_u;
    unsigned* Al  = sm_u + 8704;
    unsigned* Bsm = sm_u + 17408;
    float* sbe = (float*)(sm_u + 25600);
    float* swi = sbe + 256;
    float* swc = sbe + 512;
    float* sbg = sbe + 768;
    float* xs  = sbe + 1024;
    float* lp  = xs + 64;

    int tid = threadIdx.x;
    int wid = tid >> 5, lane = tid & 31;
    int mw = wid & 3, nh = wid >> 2;
    int r4 = lane >> 2, c4 = lane & 3;
    int m0 = blockIdx.x * 64;
    int rlo = mw * 16 + r4, rhi = rlo + 8;

    sbe[tid] = g_biasE[tid & 255];
    swi[tid] = wie[tid & 255];
    swc[tid] = wcls[tid & 255];
    sbg[tid] = bg2e[tid & 255];
    if (tid < 64) xs[tid] = bos[0];
    float bcl = bcls[0];

    float acc[16][4];
    uint2 bp[8];

#define LDCHUNK(gsrc) do { \
        const uint2* s_ = (const uint2*)(gsrc); \
        _Pragma("unroll") for (int i_ = 0; i_ < 8; i_++) bp[i_] = s_[i_ * 256 + tid]; \
    } while (0)
#define STCHUNK(BUF) do { \
        _Pragma("unroll") for (int i_ = 0; i_ < 8; i_++) \
            *(uint2*)&Bsm[(BUF) * 4096 + 2 * (i_ * 256 + tid)] = bp[i_]; \
    } while (0)

    // proj phase (A from pre-split GS fragments)
#pragma unroll
    for (int nt = 0; nt < 16; nt++)
#pragma unroll
        for (int q = 0; q < 4; q++) acc[nt][q] = 0.f;

    LDCHUNK(g_Bp);
    STCHUNK(0);
    __syncthreads();
    for (int kt = 0; kt < 50; kt++) {
        int buf = kt & 1;
        if (kt + 1 < 50) LDCHUNK(g_Bp + (size_t)(kt + 1) * 4096);
        uint2 UA  = *(const uint2*)&g_GSfh[(size_t)(m0 + rlo) * GW + kt * 8 + 2 * c4];
        uint2 VA  = *(const uint2*)&g_GSfh[(size_t)(m0 + rhi) * GW + kt * 8 + 2 * c4];
        uint2 UAl = *(const uint2*)&g_GSfl[(size_t)(m0 + rlo) * GW + kt * 8 + 2 * c4];
        uint2 VAl = *(const uint2*)&g_GSfl[(size_t)(m0 + rhi) * GW + kt * 8 + 2 * c4];
        const unsigned* bb = &Bsm[buf * 4096];
#pragma unroll
        for (int nt = 0; nt < 16; nt++) {
            int n = nh * 128 + nt * 8 + r4;
            uint2 Bh = *(const uint2*)&bb[n * 8 + 2 * c4];
            uint2 Bl = *(const uint2*)&bb[2048 + n * 8 + 2 * c4];
            mma16816(acc[nt], UA.x, VA.x, UA.y, VA.y, Bh.x, Bh.y);
            mma16816(acc[nt], UA.x, VA.x, UA.y, VA.y, Bl.x, Bl.y);
            mma16816(acc[nt], UAl.x, VAl.x, UAl.y, VAl.y, Bh.x, Bh.y);
        }
        if (kt + 1 < 50) STCHUNK(buf ^ 1);
        __syncthreads();
    }
#pragma unroll
    for (int ntp = 0; ntp < 8; ntp++) {
        int nt = ntp * 2;
        int nb0 = nh * 128 + nt * 8 + 2 * c4;
        int nb1 = nb0 + 8;
        float p00 = acc[nt][0] + sbg[nb0],   p01 = acc[nt][1] + sbg[nb0+1];
        float p10 = acc[nt+1][0] + sbg[nb1], p11 = acc[nt+1][1] + sbg[nb1+1];
        float q00 = acc[nt][2] + sbg[nb0],   q01 = acc[nt][3] + sbg[nb0+1];
        float q10 = acc[nt+1][2] + sbg[nb1], q11 = acc[nt+1][3] + sbg[nb1+1];
        unsigned he0, le0, he1, le1;
        int wlo = rlo * AST + (nh * 8 + ntp) * 8 + 2 * c4;
        int whi = rhi * AST + (nh * 8 + ntp) * 8 + 2 * c4;
        splitpack(p00, p01, he0, le0); splitpack(p10, p11, he1, le1);
        *(uint2*)&Ah[wlo] = make_uint2(he0, he1);
        *(uint2*)&Al[wlo] = make_uint2(le0, le1);
        splitpack(q00, q01, he0, le0); splitpack(q10, q11, he1, le1);
        *(uint2*)&Ah[whi] = make_uint2(he0, he1);
        *(uint2*)&Al[whi] = make_uint2(le0, le1);
    }
    __syncthreads();

    // 20 estep iterations
    for (int st = 0; st < MST; st++) {
#pragma unroll
        for (int nt = 0; nt < 16; nt++)
#pragma unroll
            for (int q = 0; q < 4; q++) acc[nt][q] = 0.f;

        LDCHUNK(g_Be);
        STCHUNK(0);
        __syncthreads();
        for (int kt = 0; kt < 16; kt++) {
            int buf = kt & 1;
            if (kt + 1 < 16) LDCHUNK(g_Be + (size_t)(kt + 1) * 4096);
            uint2 UA  = *(uint2*)&Ah[rlo * AST + kt * 8 + 2 * c4];
            uint2 VA  = *(uint2*)&Ah[rhi * AST + kt * 8 + 2 * c4];
            uint2 UAl = *(uint2*)&Al[rlo * AST + kt * 8 + 2 * c4];
            uint2 VAl = *(uint2*)&Al[rhi * AST + kt * 8 + 2 * c4];
            const unsigned* bb = &Bsm[buf * 4096];
#pragma unroll
            for (int nt = 0; nt < 16; nt++) {
                int n = nh * 128 + nt * 8 + r4;
                uint2 Bh = *(const uint2*)&bb[n * 8 + 2 * c4];
                uint2 Bl = *(const uint2*)&bb[2048 + n * 8 + 2 * c4];
                mma16816(acc[nt], UA.x, VA.x, UA.y, VA.y, Bh.x, Bh.y);
                mma16816(acc[nt], UA.x, VA.x, UA.y, VA.y, Bl.x, Bl.y);
                mma16816(acc[nt], UAl.x, VAl.x, UAl.y, VAl.y, Bh.x, Bh.y);
            }
            if (kt + 1 < 16) STCHUNK(buf ^ 1);
            __syncthreads();
        }

        float xel = xs[rlo], xeh = xs[rhi];
        float pl = 0.f, ph = 0.f;
#pragma unroll
        for (int ntp = 0; ntp < 8; ntp++) {
            int nt = ntp * 2;
            int nb0 = nh * 128 + nt * 8 + 2 * c4;
            int nb1 = nb0 + 8;
            float b00 = sbe[nb0], b01 = sbe[nb0+1], b10 = sbe[nb1], b11 = sbe[nb1+1];
            float w00 = swi[nb0], w01 = swi[nb0+1], w10 = swi[nb1], w11 = swi[nb1+1];
            float h00 = tanhfast(acc[nt][0]   + b00 + xel * w00);
            float h01 = tanhfast(acc[nt][1]   + b01 + xel * w01);
            float h10 = tanhfast(acc[nt+1][0] + b10 + xel * w10);
            float h11 = tanhfast(acc[nt+1][1] + b11 + xel * w11);
            float g00 = tanhfast(acc[nt][2]   + b00 + xeh * w00);
            float g01 = tanhfast(acc[nt][3]   + b01 + xeh * w01);
            float g10 = tanhfast(acc[nt+1][2] + b10 + xeh * w10);
            float g11 = tanhfast(acc[nt+1][3] + b11 + xeh * w11);
            float c00 = swc[nb0], c01 = swc[nb0+1], c10 = swc[nb1], c11 = swc[nb1+1];
            pl += h00 * c00 + h01 * c01 + h10 * c10 + h11 * c11;
            ph += g00 * c00 + g01 * c01 + g10 * c10 + g11 * c11;
            unsigned he0, le0, he1, le1;
            int wlo = rlo * AST + (nh * 8 + ntp) * 8 + 2 * c4;
            int whi = rhi * AST + (nh * 8 + ntp) * 8 + 2 * c4;
            splitpack(h00, h01, he0, le0); splitpack(h10, h11, he1, le1);
            *(uint2*)&Ah[wlo] = make_uint2(he0, he1);
            *(uint2*)&Al[wlo] = make_uint2(le0, le1);
            splitpack(g00, g01, he0, le0); splitpack(g10, g11, he1, le1);
            *(uint2*)&Ah[whi] = make_uint2(he0, he1);
            *(uint2*)&Al[whi] = make_uint2(le0, le1);
        }
        pl += __shfl_xor_sync(0xffffffffu, pl, 1);
        pl += __shfl_xor_sync(0xffffffffu, pl, 2);
        ph += __shfl_xor_sync(0xffffffffu, ph, 1);
        ph += __shfl_xor_sync(0xffffffffu, ph, 2);
        if (c4 == 0) {
            lp[nh * 64 + rlo] = pl;
            lp[nh * 64 + rhi] = ph;
        }
        __syncthreads();
        if (tid < 64) {
            float logit = lp[tid] + lp[64 + tid] + bcl;
            xs[tid] = logit;
            int m = m0 + tid;
            int b = m / SL, r = m % SL;
            int lim = (r < MST) ? r : MST;
            if (st < lim) {
                int start = r - MST; if (start < 0) start = 0;
                outArc[(size_t)b * SL * SL + (size_t)r * SL + start + st] = logit;
            }
        }
        __syncthreads();
    }
#undef LDCHUNK
#undef STCHUNK
}

// ---------------- arc zero-fill (early, overlapped) ----------------
__global__ void k_arc_zero(float4* __restrict__ out4) {
    size_t idx = (size_t)blockIdx.x * blockDim.x + threadIdx.x;
    size_t total = (size_t)BB * SL * SL / 4;
    if (idx < total) out4[idx] = make_float4(0.f, 0.f, 0.f, 0.f);
}

// ---------------- host launcher ----------------
extern "C" void kernel_launch(void* const* d_in, const int* in_sizes, int n_in,
                              void* d_out, int out_size) {
    const float* input  = (const float*)d_in[0];
    const float* tagemb = (const float*)d_in[1];
    const int*   mask   = (const int*)d_in[2];
    const float* sent   = (const float*)d_in[3];
    const float* Wih_f  = (const float*)d_in[4];
    const float* Whh_f  = (const float*)d_in[5];
    const float* bih_f  = (const float*)d_in[6];
    const float* bhh_f  = (const float*)d_in[7];
    const float* Wih_b  = (const float*)d_in[8];
    const float* Whh_b  = (const float*)d_in[9];
    const float* bih_b  = (const float*)d_in[10];
    const float* bhh_b  = (const float*)d_in[11];
    const float* Wg2e   = (const float*)d_in[12];
    const float* bg2e   = (const float*)d_in[13];
    const float* Wih_e  = (const float*)d_in[14];
    const float* Whh_e  = (const float*)d_in[15];
    const float* bih_e  = (const float*)d_in[16];
    const float* bhh_e  = (const float*)d_in[17];
    const float* Wcls   = (const float*)d_in[18];
    const float* bcls   = (const float*)d_in[19];
    const float* bos    = (const float*)d_in[20];
    const float* Wht    = (const float*)d_in[21];
    const float* bht    = (const float*)d_in[22];
    const float* Wdt    = (const float*)d_in[23];
    const float* bdt    = (const float*)d_in[24];
    float* out = (float*)d_out;

    float *pPre, *pbFB, *pbTag;
    unsigned *pBpre, *pBtag, *pXfh, *pXfl, *pGSfh, *pGSfl;
    cudaGetSymbolAddress((void**)&pPre, g_Pre);
    cudaGetSymbolAddress((void**)&pbFB, g_biasFB);
    cudaGetSymbolAddress((void**)&pbTag, g_biasTag);
    cudaGetSymbolAddress((void**)&pBpre, g_Bpre);
    cudaGetSymbolAddress((void**)&pBtag, g_Btag);
    cudaGetSymbolAddress((void**)&pXfh, g_Xfh);
    cudaGetSymbolAddress((void**)&pXfl, g_Xfl);
    cudaGetSymbolAddress((void**)&pGSfh, g_GSfh);
    cudaGetSymbolAddress((void**)&pGSfl, g_GSfl);

    static cudaStream_t s2 = nullptr;
    static cudaEvent_t evRoot = nullptr, evMain = nullptr, evRnn = nullptr, evTags = nullptr;
    static int inited = 0;
    if (!inited) {
        cudaFuncSetAttribute(k_eloop, cudaFuncAttributeMaxDynamicSharedMemorySize, ELOOP_SMEM);
        cudaFuncSetAttribute(k_rnn, cudaFuncAttributeMaxDynamicSharedMemorySize, RNN_SMEM);
        cudaStreamCreateWithFlags(&s2, cudaStreamNonBlocking);
        cudaEventCreateWithFlags(&evRoot, cudaEventDisableTiming);
        cudaEventCreateWithFlags(&evMain, cudaEventDisableTiming);
        cudaEventCreateWithFlags(&evRnn, cudaEventDisableTiming);
        cudaEventCreateWithFlags(&evTags, cudaEventDisableTiming);
        inited = 1;
    }

    // fork side stream
    cudaEventRecord(evRoot, 0);
    cudaStreamWaitEvent(s2, evRoot, 0);
    k_setup_side<<<(TSIDE + 255) / 256, 256, 0, s2>>>(Wg2e, Whh_e, Wht, Wdt, Whh_f, Whh_b,
                                                      bih_e, bhh_e, bht, bdt);
    {
        size_t tot4 = (size_t)BB * SL * SL / 4;
        k_arc_zero<<<(unsigned)((tot4 + 255) / 256), 256, 0, s2>>>(
            (float4*)(out + 2 * (size_t)MR * TAGL));
    }

    // main: X fragments + Pre weights + counter reset
    k_setup_main<<<(unsigned)((TMAIN + 255) / 256), 256>>>(Wih_f, Wih_b, bih_f, bhh_f,
                                                           bih_b, bhh_b, input, tagemb,
                                                           sent, mask);
    cudaEventRecord(evMain, 0);
    // Pre GEMM with progress publication (section-ordered)
    {
        dim3 grid(NPRE / 128, MR / 128);
        k_hgemm<0, 1><<<grid, 256>>>(pXfh, pXfl, pBpre, pbFB, pPre, nullptr,
                                     NPRE, DL / 16, XW, NPRE);
    }
    // rnn on side stream, overlapping Pre (gated by section counters)
    cudaStreamWaitEvent(s2, evMain, 0);
    k_rnn<<<64, 256, RNN_SMEM, s2>>>();
    cudaEventRecord(evRnn, s2);
    // tags on side stream right after rnn
    {
        dim3 grid(2, MR / 128);
        k_hgemm<2, 0><<<grid, 256, 0, s2>>>(pGSfh, pGSfl, pBtag, pbTag, out,
                                            out + (size_t)MR * TAGL,
                                            2 * TAGL, (2 * HG) / 16, GW, 2 * TAGL);
    }
    cudaEventRecord(evTags, s2);
    // eloop on main stream after rnn; band writes fused into epilogue
    cudaStreamWaitEvent(0, evRnn, 0);
    k_eloop<<<MR / 64, 256, ELOOP_SMEM>>>(Wih_e, Wcls, bcls, bos, bg2e,
                                          out + 2 * (size_t)MR * TAGL);
    // join
    cudaStreamWaitEvent(0, evTags, 0);
    (void)in_sizes; (void)n_in; (void)out_size;
}

// round 16
// speedup vs baseline: 1.0002x; 1.0002x over previous
#include <cuda_runtime.h>
#include <cuda_bf16.h>
#include <math.h>

#define BB   64
#define TL   383
#define SL   384
#define DL   896
#define HG   400
#define HEH  256
#define TAGL 128
#define MST  20
#define MR   (BB*SL)    // 24576
#define NPRE 896        // padded 2*HG
#define XW   448        // X fragment words per row (K=896)
#define GW   400        // GS fragment words per row (K=800)

// ---------------- scratch (device globals) ----------------
__device__ float g_Mf[MR];
__device__ float g_Pre[(size_t)MR*NPRE];
__device__ float g_biasFB[NPRE];
__device__ float g_biasE[HEH];
__device__ float g_biasTag[2*TAGL];
__device__ unsigned g_Xfh[(size_t)MR*XW];
__device__ unsigned g_Xfl[(size_t)MR*XW];
__device__ unsigned g_GSfh[(size_t)MR*GW];
__device__ unsigned g_GSfl[(size_t)MR*GW];
__device__ unsigned g_Be[16*2*2048];
__device__ unsigned g_Bp[50*2*2048];
__device__ unsigned g_Bpre[56*2*7168];
__device__ unsigned g_Btag[50*2*2048];
__device__ unsigned g_Bw[16*25600];
__device__ unsigned g_HXP[8*2*2*16*200];

#define CLUSTER_SYNC_() do { \
    asm volatile("barrier.cluster.arrive.aligned;" ::: "memory"); \
    asm volatile("barrier.cluster.wait.aligned;" ::: "memory"); \
} while (0)

// ---------------- helpers ----------------
__device__ __forceinline__ void splitpack(float x0, float x1, unsigned& hi, unsigned& lo) {
    __nv_bfloat16 b0 = __float2bfloat16_rn(x0);
    __nv_bfloat16 b1 = __float2bfloat16_rn(x1);
    float r0 = x0 - __bfloat162float(b0);
    float r1 = x1 - __bfloat162float(b1);
    __nv_bfloat16 c0 = __float2bfloat16_rn(r0);
    __nv_bfloat16 c1 = __float2bfloat16_rn(r1);
    hi = (unsigned)__bfloat16_as_ushort(b0) | ((unsigned)__bfloat16_as_ushort(b1) << 16);
    lo = (unsigned)__bfloat16_as_ushort(c0) | ((unsigned)__bfloat16_as_ushort(c1) << 16);
}

__device__ __forceinline__ void mma16816(float* d, unsigned a0, unsigned a1, unsigned a2,
                                         unsigned a3, unsigned b0, unsigned b1) {
    asm volatile(
        "mma.sync.aligned.m16n8k16.row.col.f32.bf16.bf16.f32 "
        "{%0,%1,%2,%3},{%4,%5,%6,%7},{%8,%9},{%0,%1,%2,%3};"
        : "+f"(d[0]), "+f"(d[1]), "+f"(d[2]), "+f"(d[3])
        : "r"(a0), "r"(a1), "r"(a2), "r"(a3), "r"(b0), "r"(b1));
}

__device__ __forceinline__ float tanhfast(float x) {
    float e = __expf(2.f * x);
    return 1.f - __fdividef(2.f, e + 1.f);
}

__device__ __forceinline__ int word_of_k(int k) {
    int kt = k >> 4, rem = k & 15;
    int s = (rem < 8) ? rem : (rem - 7);
    return kt * 8 + s;
}

// ---------------- setup (split: main / side) ----------------
#define S1 (56*2*7168)
#define S6 (NPRE)
#define TXW ((size_t)MR*XW)
#define TMAIN ((size_t)S1 + S6 + TXW + MR)

__global__ void k_setup_main(const float* __restrict__ Wih_f, const float* __restrict__ Wih_b,
                             const float* __restrict__ bih_f, const float* __restrict__ bhh_f,
                             const float* __restrict__ bih_b, const float* __restrict__ bhh_b,
                             const float* __restrict__ inp, const float* __restrict__ tag,
                             const float* __restrict__ sent, const int* __restrict__ mask) {
    size_t gidx = (size_t)blockIdx.x * blockDim.x + threadIdx.x;
    if (gidx < S1) {
        int idx = (int)gidx;
        int kt = idx / 14336, rest = idx % 14336;
        int split = rest / 7168, w = rest % 7168;
        int n = w >> 3, s = w & 7;
        int k = kt * 16 + 2 * (s >> 1) + 8 * (s & 1);
        float x0 = 0.f, x1 = 0.f;
        if (n < HG)          { x0 = Wih_f[(size_t)n * DL + k];        x1 = Wih_f[(size_t)n * DL + k + 1]; }
        else if (n < 2*HG)   { x0 = Wih_b[(size_t)(n-HG) * DL + k];   x1 = Wih_b[(size_t)(n-HG) * DL + k + 1]; }
        unsigned hi, lo; splitpack(x0, x1, hi, lo);
        g_Bpre[idx] = split ? lo : hi; return;
    }
    gidx -= S1;
    if (gidx < S6) {
        int idx = (int)gidx;
        float v = 0.f;
        if (idx < HG) v = bih_f[idx] + bhh_f[idx];
        else if (idx < 2*HG) v = bih_b[idx-HG] + bhh_b[idx-HG];
        g_biasFB[idx] = v; return;
    }
    gidx -= S6;
    if (gidx < TXW) {
        int p = (int)(gidx % XW);
        int r = (int)(gidx / XW);
        int k = (p >> 3) * 16 + 2 * ((p & 7) >> 1) + 8 * ((p & 7) & 1);
        int b = r / SL, s = r % SL;
        float x0, x1;
        if (s == 0) { x0 = sent[k]; x1 = sent[k + 1]; }
        else {
            int t = s - 1;
            if (k < 768) {
                const float* base = inp + (size_t)(b * TL + t) * 768;
                x0 = base[k]; x1 = base[k + 1];
            } else {
                const float* base = tag + (size_t)(b * TL + t) * TAGL;
                x0 = base[k - 768]; x1 = base[k - 767];
            }
        }
        unsigned hi, lo; splitpack(x0, x1, hi, lo);
        g_Xfh[gidx] = hi;
        g_Xfl[gidx] = lo;
        return;
    }
    gidx -= TXW;
    if (gidx < MR) {
        int b = (int)(gidx / SL), s = (int)(gidx % SL);
        g_Mf[gidx] = (s == 0) ? 1.0f : (float)mask[b * TL + s - 1];
    }
}

#define P2 (50*2*2048)
#define P3 (16*2*2048)
#define P4 (50*2*2048)
#define P5 (16*25600)
#define P7 (HEH)
#define P8 (2*TAGL)
#define TSIDE (P2+P3+P4+P5+P7+P8)

__global__ void k_setup_side(const float* __restrict__ Wg2e, const float* __restrict__ Whh_e,
                             const float* __restrict__ Wht,  const float* __restrict__ Wdt,
                             const float* __restrict__ Whh_f, const float* __restrict__ Whh_b,
                             const float* __restrict__ bih_e, const float* __restrict__ bhh_e,
                             const float* __restrict__ bht,   const float* __restrict__ bdt) {
    int idx = blockIdx.x * blockDim.x + threadIdx.x;
    if (idx < P2) {
        int kt = idx >> 12, rest = idx & 4095;
        int split = rest >> 11, w = rest & 2047;
        int n = w >> 3, s = w & 7;
        int k = kt * 16 + 2 * (s >> 1) + 8 * (s & 1);
        float x0 = Wg2e[(size_t)n * (2*HG) + k];
        float x1 = Wg2e[(size_t)n * (2*HG) + k + 1];
        unsigned hi, lo; splitpack(x0, x1, hi, lo);
        g_Bp[idx] = split ? lo : hi; return;
    }
    idx -= P2;
    if (idx < P3) {
        int kt = idx >> 12, rest = idx & 4095;
        int split = rest >> 11, w = rest & 2047;
        int n = w >> 3, s = w & 7;
        int k = kt * 16 + 2 * (s >> 1) + 8 * (s & 1);
        float x0 = Whh_e[(size_t)n * HEH + k];
        float x1 = Whh_e[(size_t)n * HEH + k + 1];
        unsigned hi, lo; splitpack(x0, x1, hi, lo);
        g_Be[idx] = split ? lo : hi; return;
    }
    idx -= P3;
    if (idx < P4) {
        int kt = idx >> 12, rest = idx & 4095;
        int split = rest >> 11, w = rest & 2047;
        int n = w >> 3, s = w & 7;
        int k = kt * 16 + 2 * (s >> 1) + 8 * (s & 1);
        float x0, x1;
        if (n < TAGL) { x0 = Wht[(size_t)n * (2*HG) + k];        x1 = Wht[(size_t)n * (2*HG) + k + 1]; }
        else          { x0 = Wdt[(size_t)(n-TAGL) * (2*HG) + k]; x1 = Wdt[(size_t)(n-TAGL) * (2*HG) + k + 1]; }
        unsigned hi, lo; splitpack(x0, x1, hi, lo);
        g_Btag[idx] = split ? lo : hi; return;
    }
    idx -= P4;
    if (idx < P5) {
        int ctx = idx / 25600, rest = idx % 25600;
        int dir = ctx >> 3, jgx = ctx & 7;
        int kt = rest >> 10, r2 = rest & 1023;
        int split = r2 >> 9, r3 = r2 & 511;
        int n = r3 >> 3, s = r3 & 7;
        int k = kt * 16 + 2 * (s >> 1) + 8 * (s & 1);
        float x0 = 0.f, x1 = 0.f;
        if (n < 50) {
            const float* W = dir ? Whh_b : Whh_f;
            int j = jgx * 50 + n;
            x0 = W[(size_t)j * HG + k];
            x1 = W[(size_t)j * HG + k + 1];
        }
        unsigned hi, lo; splitpack(x0, x1, hi, lo);
        g_Bw[idx] = split ? lo : hi; return;
    }
    idx -= P5;
    if (idx < P7) { g_biasE[idx] = bih_e[idx] + bhh_e[idx]; return; }
    idx -= P7;
    if (idx < P8) g_biasTag[idx] = (idx < TAGL) ? bht[idx] : bdt[idx - TAGL];
}

// ---------------- split-bf16 HMMA GEMM, 128x128 tile ----------------
template <int ACT>
__global__ __launch_bounds__(256) void k_hgemm(const unsigned* __restrict__ Afh,
                                               const unsigned* __restrict__ Afl,
                                               const unsigned* __restrict__ Bfrag,
                                               const float* __restrict__ bias,
                                               float* __restrict__ C, float* __restrict__ C2,
                                               int N, int nkt, int Kw, int Nfrag) {
    __shared__ __align__(16) unsigned Ahs[2][1024];
    __shared__ __align__(16) unsigned Als[2][1024];
    __shared__ __align__(16) unsigned Bsm[2][2048];
    int m0 = blockIdx.y * 128, n0 = blockIdx.x * 128;
    int tid = threadIdx.x, wid = tid >> 5, lane = tid & 31;
    int mw = wid & 3, nh = wid >> 2;
    int r4 = lane >> 2, c4 = lane & 3;
    int Nw8 = Nfrag * 8;

    int arow = tid >> 1, sg = (tid & 1) * 4;
    const unsigned* Aph = Afh + (size_t)(m0 + arow) * Kw + sg;
    const unsigned* Apl = Afl + (size_t)(m0 + arow) * Kw + sg;

    uint4 afh, afl;
    uint2 bf[4];
    float acc[2][8][4];
#pragma unroll
    for (int mt = 0; mt < 2; mt++)
#pragma unroll
        for (int nt = 0; nt < 8; nt++)
#pragma unroll
            for (int q = 0; q < 4; q++) acc[mt][nt][q] = 0.f;

#define HLD(KT) do { \
        afh = *(const uint4*)(Aph + (size_t)(KT) * 8); \
        afl = *(const uint4*)(Apl + (size_t)(KT) * 8); \
        _Pragma("unroll") for (int i_ = 0; i_ < 4; i_++) { \
            int lw = 2 * (i_ * 256 + tid); \
            int sp = lw >> 10, wq = lw & 1023; \
            bf[i_] = *(const uint2*)(Bfrag + (size_t)(KT) * 2 * Nw8 + (size_t)sp * Nw8 + n0 * 8 + wq); } \
    } while (0)

#define HST(BUF) do { \
        *(uint4*)&Ahs[BUF][arow * 8 + sg] = afh; \
        *(uint4*)&Als[BUF][arow * 8 + sg] = afl; \
        _Pragma("unroll") for (int i_ = 0; i_ < 4; i_++) \
            *(uint2*)&Bsm[BUF][2 * (i_ * 256 + tid)] = bf[i_]; \
    } while (0)

    HLD(0);
    HST(0);
    __syncthreads();
    for (int kt = 0; kt < nkt; kt++) {
        int buf = kt & 1;
        if (kt + 1 < nkt) HLD(kt + 1);
        uint2 Uh[2], Vh[2], Ul[2], Vl[2];
#pragma unroll
        for (int mt = 0; mt < 2; mt++) {
            int rb = mw * 32 + mt * 16 + r4;
            Uh[mt] = *(uint2*)&Ahs[buf][rb * 8 + 2 * c4];
            Vh[mt] = *(uint2*)&Ahs[buf][(rb + 8) * 8 + 2 * c4];
            Ul[mt] = *(uint2*)&Als[buf][rb * 8 + 2 * c4];
            Vl[mt] = *(uint2*)&Als[buf][(rb + 8) * 8 + 2 * c4];
        }
#pragma unroll
        for (int nt = 0; nt < 8; nt++) {
            int n = nh * 64 + nt * 8 + r4;
            uint2 Bh = *(uint2*)&Bsm[buf][n * 8 + 2 * c4];
            uint2 Bl = *(uint2*)&Bsm[buf][1024 + n * 8 + 2 * c4];
#pragma unroll
            for (int mt = 0; mt < 2; mt++) {
                mma16816(acc[mt][nt], Uh[mt].x, Vh[mt].x, Uh[mt].y, Vh[mt].y, Bh.x, Bh.y);
                mma16816(acc[mt][nt], Uh[mt].x, Vh[mt].x, Uh[mt].y, Vh[mt].y, Bl.x, Bl.y);
                mma16816(acc[mt][nt], Ul[mt].x, Vl[mt].x, Ul[mt].y, Vl[mt].y, Bh.x, Bh.y);
            }
        }
        if (kt + 1 < nkt) HST(buf ^ 1);
        __syncthreads();
    }
#undef HLD
#undef HST

#pragma unroll
    for (int nt = 0; nt < 8; nt++) {
        int colL = nh * 64 + nt * 8 + 2 * c4;
        float b0 = bias[n0 + colL], b1 = bias[n0 + colL + 1];
#pragma unroll
        for (int mt = 0; mt < 2; mt++) {
            int r = m0 + mw * 32 + mt * 16 + r4;
            float v0 = acc[mt][nt][0] + b0, v1 = acc[mt][nt][1] + b1;
            float v2 = acc[mt][nt][2] + b0, v3 = acc[mt][nt][3] + b1;
            if (ACT == 2) {
                v0 = (v0 > 0.f) ? v0 : expm1f(v0);
                v1 = (v1 > 0.f) ? v1 : expm1f(v1);
                v2 = (v2 > 0.f) ? v2 : expm1f(v2);
                v3 = (v3 > 0.f) ? v3 : expm1f(v3);
                float* dst = (blockIdx.x == 0) ? C : C2;
                *(float2*)(dst + (size_t)r * TAGL + colL)       = make_float2(v0, v1);
                *(float2*)(dst + (size_t)(r + 8) * TAGL + colL) = make_float2(v2, v3);
            } else {
                *(float2*)(C + (size_t)r * N + n0 + colL)       = make_float2(v0, v1);
                *(float2*)(C + (size_t)(r + 8) * N + n0 + colL) = make_float2(v2, v3);
            }
        }
    }
}

// ---------------- HMMA bidirectional masked RNN (8 clusters of 8, 16 batches/CTA) ----------------
#define RAS 200
#define RNN_SMEM ((25600 + 2*16*RAS) * 4)

__global__ void __cluster_dims__(8, 1, 1) __launch_bounds__(256, 1) k_rnn() {
    extern __shared__ unsigned rsm[];
    unsigned* Bs = rsm;
    unsigned* Ah = rsm + 25600;
    unsigned* Al = Ah + 16 * RAS;

    int bx = blockIdx.x;
    int cl = bx >> 3, jg = bx & 7;
    int dir = cl >> 2, bg = cl & 3;
    int bbase = bg * 16;
    int tid = threadIdx.x, wid = tid >> 5, lane = tid & 31;
    int ng = wid;
    int r4 = lane >> 2, c4 = lane & 3;
    int rlo = r4, rhi = r4 + 8;

    {
        const uint2* bsrc = (const uint2*)(g_Bw + (size_t)(dir * 8 + jg) * 25600);
#pragma unroll
        for (int i = 0; i < 50; i++) {
            int idx = tid + i * 256;
            uint2 v = __ldcg(bsrc + idx);
            *(uint2*)&Bs[2 * idx] = v;
        }
    }
    {
        unsigned* hxp0 = g_HXP + (size_t)(cl * 2 + 0) * 6400;
        for (int idx = tid; idx < 800; idx += 256) {
            int split = idx / 400, rest = idx % 400;
            int b = rest / 25, w = rest % 25;
            int p = word_of_k(jg * 50 + 2 * w);
            __stcg(&hxp0[split * 3200 + b * 200 + p], 0u);
        }
    }
    __syncthreads();
    CLUSTER_SYNC_();

    int jl = ng * 8 + 2 * c4;
    int valid = (jl < 50);
    int wdp = word_of_k(jg * 50 + jl);
    int wdg = word_of_k(dir * 400 + jg * 50 + jl);
    float h[2][2];
#pragma unroll
    for (int a = 0; a < 2; a++) { h[a][0] = 0.f; h[a][1] = 0.f; }

    for (int tv = 0; tv < SL; tv++) {
        int t = dir ? (SL - 1 - tv) : tv;
        int pp = tv & 1;
        const uint2* src = (const uint2*)(g_HXP + (size_t)(cl * 2 + pp) * 6400);
        uint2 bp[13];
#pragma unroll
        for (int i = 0; i < 13; i++) {
            int idx = tid + i * 256;
            if (idx < 3200) {
                int split = idx / 1600, rest = idx % 1600;
                int b = rest / 100, wp = rest % 100;
                bp[i] = __ldcg(src + (size_t)split * 1600 + b * 100 + wp);
            }
        }
        float mv[2];
        mv[0] = g_Mf[(bbase + rlo) * SL + t];
        mv[1] = g_Mf[(bbase + rhi) * SL + t];
        float2 pre[2];
#pragma unroll
        for (int rq = 0; rq < 2; rq++) {
            int R = rq ? rhi : rlo;
            pre[rq] = *(const float2*)(g_Pre + (size_t)((bbase + R) * SL + t) * NPRE + dir * HG + jg * 50 + jl);
        }
#pragma unroll
        for (int i = 0; i < 13; i++) {
            int idx = tid + i * 256;
            if (idx < 3200) {
                int split = idx / 1600, rest = idx % 1600;
                int b = rest / 100, wp = rest % 100;
                unsigned* dst = split ? Al : Ah;
                *(uint2*)&dst[b * RAS + wp * 2] = bp[i];
            }
        }
        __syncthreads();

        float fa[2][3][4];
#pragma unroll
        for (int px = 0; px < 2; px++)
#pragma unroll
            for (int tm = 0; tm < 3; tm++)
#pragma unroll
                for (int z = 0; z < 4; z++) fa[px][tm][z] = 0.f;
#pragma unroll
        for (int kt = 0; kt < 25; kt++) {
            int px = kt & 1;
            uint2 UA  = *(uint2*)&Ah[rlo * RAS + kt * 8 + 2 * c4];
            uint2 VA  = *(uint2*)&Ah[rhi * RAS + kt * 8 + 2 * c4];
            uint2 UAl = *(uint2*)&Al[rlo * RAS + kt * 8 + 2 * c4];
            uint2 VAl = *(uint2*)&Al[rhi * RAS + kt * 8 + 2 * c4];
            int n = ng * 8 + r4;
            uint2 Bh = *(uint2*)&Bs[(kt * 2) * 512 + n * 8 + 2 * c4];
            uint2 Bl = *(uint2*)&Bs[(kt * 2 + 1) * 512 + n * 8 + 2 * c4];
            mma16816(fa[px][0], UA.x, VA.x, UA.y, VA.y, Bh.x, Bh.y);
            mma16816(fa[px][1], UA.x, VA.x, UA.y, VA.y, Bl.x, Bl.y);
            mma16816(fa[px][2], UAl.x, VAl.x, UAl.y, VAl.y, Bh.x, Bh.y);
        }
        float acc[4];
#pragma unroll
        for (int z = 0; z < 4; z++)
            acc[z] = ((fa[0][0][z] + fa[0][1][z]) + (fa[0][2][z] + fa[1][0][z]))
                   + (fa[1][1][z] + fa[1][2][z]);
        // no CTA sync here: the end-of-step cluster barrier covers it

        unsigned* dsth = g_HXP + (size_t)(cl * 2 + (pp ^ 1)) * 6400;
#pragma unroll
        for (int rq = 0; rq < 2; rq++) {
            int R = rq ? rhi : rlo;
            float mt = mv[rq], om = 1.f - mt;
            float u0 = mt * tanhfast(pre[rq].x + acc[rq * 2 + 0]) + om * h[rq][0];
            float u1 = mt * tanhfast(pre[rq].y + acc[rq * 2 + 1]) + om * h[rq][1];
            h[rq][0] = u0; h[rq][1] = u1;
            if (valid) {
                unsigned hi, lo; splitpack(u0, u1, hi, lo);
                __stcg(&dsth[R * 200 + wdp], hi);
                __stcg(&dsth[3200 + R * 200 + wdp], lo);
                size_t row = (size_t)((bbase + R) * SL + t);
                unsigned gh = (mt != 0.f) ? hi : 0u;
                unsigned gl = (mt != 0.f) ? lo : 0u;
                __stcg(&g_GSfh[row * GW + wdg], gh);
                __stcg(&g_GSfl[row * GW + wdg], gl);
            }
        }
        CLUSTER_SYNC_();
    }
}

// ---------------- tensor-core proj + 20-step estep loop (64 rows/CTA, 2 CTAs/SM) ----------------
#define AST 136
#define ELOOP_WORDS (2*8704 + 8192 + 1024 + 64 + 128)
#define ELOOP_SMEM  (ELOOP_WORDS * 4)

__global__ __launch_bounds__(256, 2) void k_eloop(const float* __restrict__ wie,
                                                  const float* __restrict__ wcls,
                                                  const float* __restrict__ bcls,
                                                  const float* __restrict__ bos,
                                                  const float* __restrict__ bg2e,
                                                  float* __restrict__ outArc) {
    extern __shared__ unsigned sm_u[];
    unsigned* Ah  = sm_u;
    unsigned* Al  = sm_u + 8704;
    unsigned* Bsm = sm_u + 17408;
    float* sbe = (float*)(sm_u + 25600);
    float* swi = sbe + 256;
    float* swc = sbe + 512;
    float* sbg = sbe + 768;
    float* xs  = sbe + 1024;
    float* lp  = xs + 64;

    int tid = threadIdx.x;
    int wid = tid >> 5, lane = tid & 31;
    int mw = wid & 3, nh = wid >> 2;
    int r4 = lane >> 2, c4 = lane & 3;
    int m0 = blockIdx.x * 64;
    int rlo = mw * 16 + r4, rhi = rlo + 8;

    sbe[tid] = g_biasE[tid & 255];
    swi[tid] = wie[tid & 255];
    swc[tid] = wcls[tid & 255];
    sbg[tid] = bg2e[tid & 255];
    if (tid < 64) xs[tid] = bos[0];
    float bcl = bcls[0];

    float acc[16][4];
    uint2 bp[8];

#define LDCHUNK(gsrc) do { \
        const uint2* s_ = (const uint2*)(gsrc); \
        _Pragma("unroll") for (int i_ = 0; i_ < 8; i_++) bp[i_] = s_[i_ * 256 + tid]; \
    } while (0)
#define STCHUNK(BUF) do { \
        _Pragma("unroll") for (int i_ = 0; i_ < 8; i_++) \
            *(uint2*)&Bsm[(BUF) * 4096 + 2 * (i_ * 256 + tid)] = bp[i_]; \
    } while (0)

    // proj phase (A from pre-split GS fragments)
#pragma unroll
    for (int nt = 0; nt < 16; nt++)
#pragma unroll
        for (int q = 0; q < 4; q++) acc[nt][q] = 0.f;

    LDCHUNK(g_Bp);
    STCHUNK(0);
    __syncthreads();
    for (int kt = 0; kt < 50; kt++) {
        int buf = kt & 1;
        if (kt + 1 < 50) LDCHUNK(g_Bp + (size_t)(kt + 1) * 4096);
        uint2 UA  = *(const uint2*)&g_GSfh[(size_t)(m0 + rlo) * GW + kt * 8 + 2 * c4];
        uint2 VA  = *(const uint2*)&g_GSfh[(size_t)(m0 + rhi) * GW + kt * 8 + 2 * c4];
        uint2 UAl = *(const uint2*)&g_GSfl[(size_t)(m0 + rlo) * GW + kt * 8 + 2 * c4];
        uint2 VAl = *(const uint2*)&g_GSfl[(size_t)(m0 + rhi) * GW + kt * 8 + 2 * c4];
        const unsigned* bb = &Bsm[buf * 4096];
#pragma unroll
        for (int nt = 0; nt < 16; nt++) {
            int n = nh * 128 + nt * 8 + r4;
            uint2 Bh = *(const uint2*)&bb[n * 8 + 2 * c4];
            uint2 Bl = *(const uint2*)&bb[2048 + n * 8 + 2 * c4];
            mma16816(acc[nt], UA.x, VA.x, UA.y, VA.y, Bh.x, Bh.y);
            mma16816(acc[nt], UA.x, VA.x, UA.y, VA.y, Bl.x, Bl.y);
            mma16816(acc[nt], UAl.x, VAl.x, UAl.y, VAl.y, Bh.x, Bh.y);
        }
        if (kt + 1 < 50) STCHUNK(buf ^ 1);
        __syncthreads();
    }
#pragma unroll
    for (int ntp = 0; ntp < 8; ntp++) {
        int nt = ntp * 2;
        int nb0 = nh * 128 + nt * 8 + 2 * c4;
        int nb1 = nb0 + 8;
        float p00 = acc[nt][0] + sbg[nb0],   p01 = acc[nt][1] + sbg[nb0+1];
        float p10 = acc[nt+1][0] + sbg[nb1], p11 = acc[nt+1][1] + sbg[nb1+1];
        float q00 = acc[nt][2] + sbg[nb0],   q01 = acc[nt][3] + sbg[nb0+1];
        float q10 = acc[nt+1][2] + sbg[nb1], q11 = acc[nt+1][3] + sbg[nb1+1];
        unsigned he0, le0, he1, le1;
        int wlo = rlo * AST + (nh * 8 + ntp) * 8 + 2 * c4;
        int whi = rhi * AST + (nh * 8 + ntp) * 8 + 2 * c4;
        splitpack(p00, p01, he0, le0); splitpack(p10, p11, he1, le1);
        *(uint2*)&Ah[wlo] = make_uint2(he0, he1);
        *(uint2*)&Al[wlo] = make_uint2(le0, le1);
        splitpack(q00, q01, he0, le0); splitpack(q10, q11, he1, le1);
        *(uint2*)&Ah[whi] = make_uint2(he0, he1);
        *(uint2*)&Al[whi] = make_uint2(le0, le1);
    }
    __syncthreads();

    // 20 estep iterations
    for (int st = 0; st < MST; st++) {
#pragma unroll
        for (int nt = 0; nt < 16; nt++)
#pragma unroll
            for (int q = 0; q < 4; q++) acc[nt][q] = 0.f;

        LDCHUNK(g_Be);
        STCHUNK(0);
        __syncthreads();
        for (int kt = 0; kt < 16; kt++) {
            int buf = kt & 1;
            if (kt + 1 < 16) LDCHUNK(g_Be + (size_t)(kt + 1) * 4096);
            uint2 UA  = *(uint2*)&Ah[rlo * AST + kt * 8 + 2 * c4];
            uint2 VA  = *(uint2*)&Ah[rhi * AST + kt * 8 + 2 * c4];
            uint2 UAl = *(uint2*)&Al[rlo * AST + kt * 8 + 2 * c4];
            uint2 VAl = *(uint2*)&Al[rhi * AST + kt * 8 + 2 * c4];
            const unsigned* bb = &Bsm[buf * 4096];
#pragma unroll
            for (int nt = 0; nt < 16; nt++) {
                int n = nh * 128 + nt * 8 + r4;
                uint2 Bh = *(const uint2*)&bb[n * 8 + 2 * c4];
                uint2 Bl = *(const uint2*)&bb[2048 + n * 8 + 2 * c4];
                mma16816(acc[nt], UA.x, VA.x, UA.y, VA.y, Bh.x, Bh.y);
                mma16816(acc[nt], UA.x, VA.x, UA.y, VA.y, Bl.x, Bl.y);
                mma16816(acc[nt], UAl.x, VAl.x, UAl.y, VAl.y, Bh.x, Bh.y);
            }
            if (kt + 1 < 16) STCHUNK(buf ^ 1);
            __syncthreads();
        }

        float xel = xs[rlo], xeh = xs[rhi];
        float pl = 0.f, ph = 0.f;
#pragma unroll
        for (int ntp = 0; ntp < 8; ntp++) {
            int nt = ntp * 2;
            int nb0 = nh * 128 + nt * 8 + 2 * c4;
            int nb1 = nb0 + 8;
            float b00 = sbe[nb0], b01 = sbe[nb0+1], b10 = sbe[nb1], b11 = sbe[nb1+1];
            float w00 = swi[nb0], w01 = swi[nb0+1], w10 = swi[nb1], w11 = swi[nb1+1];
            float h00 = tanhfast(acc[nt][0]   + b00 + xel * w00);
            float h01 = tanhfast(acc[nt][1]   + b01 + xel * w01);
            float h10 = tanhfast(acc[nt+1][0] + b10 + xel * w10);
            float h11 = tanhfast(acc[nt+1][1] + b11 + xel * w11);
            float g00 = tanhfast(acc[nt][2]   + b00 + xeh * w00);
            float g01 = tanhfast(acc[nt][3]   + b01 + xeh * w01);
            float g10 = tanhfast(acc[nt+1][2] + b10 + xeh * w10);
            float g11 = tanhfast(acc[nt+1][3] + b11 + xeh * w11);
            float c00 = swc[nb0], c01 = swc[nb0+1], c10 = swc[nb1], c11 = swc[nb1+1];
            pl += h00 * c00 + h01 * c01 + h10 * c10 + h11 * c11;
            ph += g00 * c00 + g01 * c01 + g10 * c10 + g11 * c11;
            unsigned he0, le0, he1, le1;
            int wlo = rlo * AST + (nh * 8 + ntp) * 8 + 2 * c4;
            int whi = rhi * AST + (nh * 8 + ntp) * 8 + 2 * c4;
            splitpack(h00, h01, he0, le0); splitpack(h10, h11, he1, le1);
            *(uint2*)&Ah[wlo] = make_uint2(he0, he1);
            *(uint2*)&Al[wlo] = make_uint2(le0, le1);
            splitpack(g00, g01, he0, le0); splitpack(g10, g11, he1, le1);
            *(uint2*)&Ah[whi] = make_uint2(he0, he1);
            *(uint2*)&Al[whi] = make_uint2(le0, le1);
        }
        pl += __shfl_xor_sync(0xffffffffu, pl, 1);
        pl += __shfl_xor_sync(0xffffffffu, pl, 2);
        ph += __shfl_xor_sync(0xffffffffu, ph, 1);
        ph += __shfl_xor_sync(0xffffffffu, ph, 2);
        if (c4 == 0) {
            lp[nh * 64 + rlo] = pl;
            lp[nh * 64 + rhi] = ph;
        }
        __syncthreads();
        if (tid < 64) {
            float logit = lp[tid] + lp[64 + tid] + bcl;
            xs[tid] = logit;
            // fused arc band write
            int m = m0 + tid;
            int b = m / SL, r = m % SL;
            int lim = (r < MST) ? r : MST;
            if (st < lim) {
                int start = r - MST; if (start < 0) start = 0;
                outArc[(size_t)b * SL * SL + (size_t)r * SL + start + st] = logit;
            }
        }
        __syncthreads();
    }
#undef LDCHUNK
#undef STCHUNK
}

// ---------------- arc zero-fill (early, overlapped) ----------------
__global__ void k_arc_zero(float4* __restrict__ out4) {
    size_t idx = (size_t)blockIdx.x * blockDim.x + threadIdx.x;
    size_t total = (size_t)BB * SL * SL / 4;
    if (idx < total) out4[idx] = make_float4(0.f, 0.f, 0.f, 0.f);
}

// ---------------- host launcher ----------------
extern "C" void kernel_launch(void* const* d_in, const int* in_sizes, int n_in,
                              void* d_out, int out_size) {
    const float* input  = (const float*)d_in[0];
    const float* tagemb = (const float*)d_in[1];
    const int*   mask   = (const int*)d_in[2];
    const float* sent   = (const float*)d_in[3];
    const float* Wih_f  = (const float*)d_in[4];
    const float* Whh_f  = (const float*)d_in[5];
    const float* bih_f  = (const float*)d_in[6];
    const float* bhh_f  = (const float*)d_in[7];
    const float* Wih_b  = (const float*)d_in[8];
    const float* Whh_b  = (const float*)d_in[9];
    const float* bih_b  = (const float*)d_in[10];
    const float* bhh_b  = (const float*)d_in[11];
    const float* Wg2e   = (const float*)d_in[12];
    const float* bg2e   = (const float*)d_in[13];
    const float* Wih_e  = (const float*)d_in[14];
    const float* Whh_e  = (const float*)d_in[15];
    const float* bih_e  = (const float*)d_in[16];
    const float* bhh_e  = (const float*)d_in[17];
    const float* Wcls   = (const float*)d_in[18];
    const float* bcls   = (const float*)d_in[19];
    const float* bos    = (const float*)d_in[20];
    const float* Wht    = (const float*)d_in[21];
    const float* bht    = (const float*)d_in[22];
    const float* Wdt    = (const float*)d_in[23];
    const float* bdt    = (const float*)d_in[24];
    float* out = (float*)d_out;

    float *pPre, *pbFB, *pbTag;
    unsigned *pBpre, *pBtag, *pXfh, *pXfl, *pGSfh, *pGSfl;
    cudaGetSymbolAddress((void**)&pPre, g_Pre);
    cudaGetSymbolAddress((void**)&pbFB, g_biasFB);
    cudaGetSymbolAddress((void**)&pbTag, g_biasTag);
    cudaGetSymbolAddress((void**)&pBpre, g_Bpre);
    cudaGetSymbolAddress((void**)&pBtag, g_Btag);
    cudaGetSymbolAddress((void**)&pXfh, g_Xfh);
    cudaGetSymbolAddress((void**)&pXfl, g_Xfl);
    cudaGetSymbolAddress((void**)&pGSfh, g_GSfh);
    cudaGetSymbolAddress((void**)&pGSfl, g_GSfl);

    static cudaStream_t s2 = nullptr;
    static cudaEvent_t evRoot = nullptr, evSide = nullptr, evGS = nullptr, evTags = nullptr;
    static int inited = 0;
    if (!inited) {
        cudaFuncSetAttribute(k_eloop, cudaFuncAttributeMaxDynamicSharedMemorySize, ELOOP_SMEM);
        cudaFuncSetAttribute(k_rnn, cudaFuncAttributeMaxDynamicSharedMemorySize, RNN_SMEM);
        cudaStreamCreateWithFlags(&s2, cudaStreamNonBlocking);
        cudaEventCreateWithFlags(&evRoot, cudaEventDisableTiming);
        cudaEventCreateWithFlags(&evSide, cudaEventDisableTiming);
        cudaEventCreateWithFlags(&evGS, cudaEventDisableTiming);
        cudaEventCreateWithFlags(&evTags, cudaEventDisableTiming);
        inited = 1;
    }

    // fork side stream: side weight prep + arc zero-fill (overlaps main setup + Pre)
    cudaEventRecord(evRoot, 0);
    cudaStreamWaitEvent(s2, evRoot, 0);
    k_setup_side<<<(TSIDE + 255) / 256, 256, 0, s2>>>(Wg2e, Whh_e, Wht, Wdt, Whh_f, Whh_b,
                                                      bih_e, bhh_e, bht, bdt);
    {
        size_t tot4 = (size_t)BB * SL * SL / 4;
        k_arc_zero<<<(unsigned)((tot4 + 255) / 256), 256, 0, s2>>>(
            (float4*)(out + 2 * (size_t)MR * TAGL));
    }
    cudaEventRecord(evSide, s2);

    // main: X fragments + Pre weights
    k_setup_main<<<(unsigned)((TMAIN + 255) / 256), 256>>>(Wih_f, Wih_b, bih_f, bhh_f,
                                                           bih_b, bhh_b, input, tagemb,
                                                           sent, mask);
    // Pre GEMM (serial — overlap with rnn proved contention-neutral)
    {
        dim3 grid(NPRE / 128, MR / 128);
        k_hgemm<0><<<grid, 256>>>(pXfh, pXfl, pBpre, pbFB, pPre, nullptr,
                                  NPRE, DL / 16, XW, NPRE);
    }
    // join side (g_Bw/biases needed), then recurrence on main
    cudaStreamWaitEvent(0, evSide, 0);
    k_rnn<<<64, 256, RNN_SMEM>>>();
    // fork tags (depends only on GS fragments)
    cudaEventRecord(evGS, 0);
    cudaStreamWaitEvent(s2, evGS, 0);
    {
        dim3 grid(2, MR / 128);
        k_hgemm<2><<<grid, 256, 0, s2>>>(pGSfh, pGSfl, pBtag, pbTag, out,
                                         out + (size_t)MR * TAGL,
                                         2 * TAGL, (2 * HG) / 16, GW, 2 * TAGL);
    }
    cudaEventRecord(evTags, s2);
    // eloop on main; arc band writes fused into epilogue
    k_eloop<<<MR / 64, 256, ELOOP_SMEM>>>(Wih_e, Wcls, bcls, bos, bg2e,
                                          out + 2 * (size_t)MR * TAGL);
    // join
    cudaStreamWaitEvent(0, evTags, 0);
    (void)in_sizes; (void)n_in; (void)out_size;
}